// round 3
// baseline (speedup 1.0000x reference)
#include <cuda_runtime.h>
#include <math.h>
#include <stdint.h>

#define NN   100000      // nodes
#define DD   128         // feature dim
#define EE   800000      // edges per etype
#define QKV  384         // q|k|v outputs per node per etype
#define BM   32          // node tile for gemm_attn

// ---------------- scratch (no allocs allowed -> __device__ globals) ----------------
__device__ float g_Wf[2 * DD * QKV];        // folded weights, [e][k][j] j = q(0..127)|k(128..255)|v(256..383)
__device__ float g_bias[2 * QKV];           // folded biases
__device__ float g_Wh[(size_t)NN * DD];     // per-etype attention output (reused across etypes)
__device__ float g_tot[2 * (size_t)NN * DD];// per-etype scatter sums
__device__ float g_deg[2 * NN];             // per-etype in-degrees

// ---------------- zero scratch accumulators ----------------
__global__ void zero_scratch() {
    const size_t stride = (size_t)gridDim.x * blockDim.x;
    size_t i0 = (size_t)blockIdx.x * blockDim.x + threadIdx.x;
    float4 z = make_float4(0.f, 0.f, 0.f, 0.f);
    float4* t4 = reinterpret_cast<float4*>(g_tot);
    const size_t nt4 = (2 * (size_t)NN * DD) / 4;
    for (size_t i = i0; i < nt4; i += stride) t4[i] = z;
    float4* d4 = reinterpret_cast<float4*>(g_deg);
    const size_t nd4 = (2 * (size_t)NN) / 4;
    for (size_t i = i0; i < nd4; i += stride) d4[i] = z;
}

// ---------------- fold weights: A = Wt[e] @ Xw[e]  (X in {Q,K,V}) ----------------
// grid: 256 blocks (e*128 + k), 384 threads (j)
__global__ void fold_w(const float* __restrict__ Wt, const float* __restrict__ Kw,
                       const float* __restrict__ Qw, const float* __restrict__ Vw) {
    const int b = blockIdx.x;
    const int e = b >> 7, kk = b & 127;
    const int j = threadIdx.x;
    const int sel = j >> 7, jj = j & 127;
    const float* X = (sel == 0 ? Qw : (sel == 1 ? Kw : Vw)) + e * DD * DD;
    const float* wrow = Wt + e * DD * DD + kk * DD;
    float s = 0.f;
#pragma unroll 8
    for (int m = 0; m < DD; m++) s += wrow[m] * X[m * DD + jj];
    g_Wf[(e * DD + kk) * QKV + j] = s;
}

// ---------------- fold biases: b' = bt[e] @ Xw[e] + Xb[e] ----------------
// grid: 2 blocks (e), 384 threads (j)
__global__ void fold_b(const float* __restrict__ bt,
                       const float* __restrict__ Kw, const float* __restrict__ Kb,
                       const float* __restrict__ Qw, const float* __restrict__ Qb,
                       const float* __restrict__ Vw, const float* __restrict__ Vb) {
    const int e = blockIdx.x;
    const int j = threadIdx.x;
    const int sel = j >> 7, jj = j & 127;
    const float* X  = (sel == 0 ? Qw : (sel == 1 ? Kw : Vw)) + e * DD * DD;
    const float* Xb = (sel == 0 ? Qb : (sel == 1 ? Kb : Vb)) + e * DD;
    float s = Xb[jj];
#pragma unroll 8
    for (int m = 0; m < DD; m++) s += bt[e * DD + m] * X[m * DD + jj];
    g_bias[e * QKV + j] = s;
}

// ---------------- fused qkv-GEMM + cross-head attention ----------------
// Block: 256 threads, tile = 32 nodes x 384 outputs, K = 128.
// Dynamic smem layout:
//   phase 1 (GEMM): As[128][33] (4224 f) | Bs[16][384] (6144 f)
//   phase 2 (attn): S[32][385] (12320 f) | SC[32][16] (512 f)   -> 12832 floats total
#define GEMM_SMEM_FLOATS 12832
__global__ __launch_bounds__(256, 2) void gemm_attn(const float* __restrict__ feat, int e) {
    extern __shared__ float sm[];
    float* As = sm;              // [k][n], stride 33
    float* Bs = sm + 128 * 33;   // [kk][j]
    const int t  = threadIdx.x;
    const int tx = t & 31;       // output lane: j = tx + 32*u
    const int ty = t >> 5;       // node group: nodes ty*4 .. ty*4+3
    const int base = blockIdx.x * BM;
    const float* Wf = g_Wf + e * DD * QKV;

    float acc[4][12];
#pragma unroll
    for (int u = 0; u < 12; u++) {
        float b = g_bias[e * QKV + tx + 32 * u];
#pragma unroll
        for (int i = 0; i < 4; i++) acc[i][u] = b;
    }

    // load feat tile transposed into As[k][n]
    for (int idx = t; idx < BM * DD; idx += 256) {
        int n = idx >> 7, k = idx & 127;
        As[k * 33 + n] = feat[(size_t)(base + n) * DD + k];
    }

    for (int kc = 0; kc < 8; kc++) {
        for (int idx = t; idx < 16 * QKV; idx += 256) {
            int kk = idx / QKV;
            int j  = idx - kk * QKV;
            Bs[idx] = Wf[(kc * 16 + kk) * QKV + j];
        }
        __syncthreads();
#pragma unroll
        for (int kk = 0; kk < 16; kk++) {
            const float* arow = &As[(kc * 16 + kk) * 33 + ty * 4];
            float a0 = arow[0], a1 = arow[1], a2 = arow[2], a3 = arow[3];
#pragma unroll
            for (int u = 0; u < 12; u++) {
                float bb = Bs[kk * QKV + tx + 32 * u];
                acc[0][u] += a0 * bb;
                acc[1][u] += a1 * bb;
                acc[2][u] += a2 * bb;
                acc[3][u] += a3 * bb;
            }
        }
        __syncthreads();
    }

    // stage qkv to shared (overlaps As/Bs; accs are in regs, last barrier passed)
    float* S  = sm;              // [n][385]
    float* SC = sm + BM * 385;   // [n][16] scores
#pragma unroll
    for (int u = 0; u < 12; u++)
#pragma unroll
        for (int i = 0; i < 4; i++)
            S[(ty * 4 + i) * 385 + tx + 32 * u] = acc[i][u];
    __syncthreads();

    // attention: 8 threads per node; H=4, HD=32
    const int node = t >> 3;
    const int r    = t & 7;
    const float* qn = S + node * 385;
#pragma unroll
    for (int pi = 0; pi < 2; pi++) {
        int p = 2 * r + pi;
        int h = p >> 2, g = p & 3;
        float s = 0.f;
#pragma unroll
        for (int d = 0; d < 32; d++)
            s += qn[h * 32 + d] * qn[128 + g * 32 + d];
        SC[node * 16 + p] = s * 0.17677669529663687f;   // 1/sqrt(32)
    }
    __syncthreads();
    {
        int h = r >> 1;
        int dbase = (r & 1) * 16;
        float s0 = SC[node * 16 + h * 4 + 0];
        float s1 = SC[node * 16 + h * 4 + 1];
        float s2 = SC[node * 16 + h * 4 + 2];
        float s3 = SC[node * 16 + h * 4 + 3];
        float mx = fmaxf(fmaxf(s0, s1), fmaxf(s2, s3));
        float e0 = __expf(s0 - mx), e1 = __expf(s1 - mx);
        float e2 = __expf(s2 - mx), e3 = __expf(s3 - mx);
        float inv = 1.f / (e0 + e1 + e2 + e3);
        e0 *= inv; e1 *= inv; e2 *= inv; e3 *= inv;
        float outv[16];
#pragma unroll
        for (int d = 0; d < 16; d++) {
            int c = dbase + d;
            outv[d] = e0 * qn[256 +  0 + c] + e1 * qn[256 + 32 + c]
                    + e2 * qn[256 + 64 + c] + e3 * qn[256 + 96 + c];
        }
        float4* dp = reinterpret_cast<float4*>(g_Wh + (size_t)(base + node) * DD + h * 32 + dbase);
#pragma unroll
        for (int v = 0; v < 4; v++)
            dp[v] = make_float4(outv[4 * v], outv[4 * v + 1], outv[4 * v + 2], outv[4 * v + 3]);
    }
}

// ---------------- edge scatter: one warp per edge, vector f32x4 reduction ----------------
__device__ __forceinline__ void red_add_v4(float* p, float4 v) {
    asm volatile("red.global.add.v4.f32 [%0], {%1,%2,%3,%4};"
                 :: "l"(p), "f"(v.x), "f"(v.y), "f"(v.z), "f"(v.w) : "memory");
}

__global__ void scatter_edges(const int* __restrict__ src, const int* __restrict__ dst, int e) {
    const int gw   = (int)((blockIdx.x * (unsigned)blockDim.x + threadIdx.x) >> 5);
    const int lane = threadIdx.x & 31;
    if (gw >= EE) return;
    const int s = src[gw];
    const int d = dst[gw];
    if (lane == 0) atomicAdd(&g_deg[e * NN + d], 1.0f);
    const float4 v = *reinterpret_cast<const float4*>(g_Wh + (size_t)s * DD + lane * 4);
    red_add_v4(g_tot + (size_t)e * NN * DD + (size_t)d * DD + lane * 4, v);
}

// ---------------- residual + mean aggregation + LayerNorm ----------------
__global__ void finalize(const float* __restrict__ feat,
                         const float* __restrict__ ln_g, const float* __restrict__ ln_b,
                         float* __restrict__ out) {
    const int node = (int)((blockIdx.x * (unsigned)blockDim.x + threadIdx.x) >> 5);
    const int lane = threadIdx.x & 31;
    if (node >= NN) return;
    const size_t off = (size_t)node * DD + lane * 4;
    float4 f  = *reinterpret_cast<const float4*>(feat + off);
    float4 t0 = *reinterpret_cast<const float4*>(g_tot + off);
    float4 t1 = *reinterpret_cast<const float4*>(g_tot + (size_t)NN * DD + off);
    float r0 = 1.f / fmaxf(g_deg[node], 1.f);
    float r1 = 1.f / fmaxf(g_deg[NN + node], 1.f);
    float h0 = f.x + t0.x * r0 + t1.x * r1;
    float h1 = f.y + t0.y * r0 + t1.y * r1;
    float h2 = f.z + t0.z * r0 + t1.z * r1;
    float h3 = f.w + t0.w * r0 + t1.w * r1;
    float sum = h0 + h1 + h2 + h3;
    float ssq = h0 * h0 + h1 * h1 + h2 * h2 + h3 * h3;
#pragma unroll
    for (int o = 16; o; o >>= 1) {
        sum += __shfl_xor_sync(0xffffffffu, sum, o);
        ssq += __shfl_xor_sync(0xffffffffu, ssq, o);
    }
    const float mu  = sum * (1.f / 128.f);
    const float var = ssq * (1.f / 128.f) - mu * mu;
    const float rs  = rsqrtf(var + 1e-5f);
    float4 g = *reinterpret_cast<const float4*>(ln_g + lane * 4);
    float4 b = *reinterpret_cast<const float4*>(ln_b + lane * 4);
    float4 o4;
    o4.x = (h0 - mu) * rs * g.x + b.x;
    o4.y = (h1 - mu) * rs * g.y + b.y;
    o4.z = (h2 - mu) * rs * g.z + b.z;
    o4.w = (h3 - mu) * rs * g.w + b.w;
    *reinterpret_cast<float4*>(out + off) = o4;
}

// ---------------- launch ----------------
extern "C" void kernel_launch(void* const* d_in, const int* in_sizes, int n_in,
                              void* d_out, int out_size) {
    const float* feat = (const float*)d_in[0];
    const int*   src  = (const int*)  d_in[1];
    const int*   dst  = (const int*)  d_in[2];
    const float* Wt   = (const float*)d_in[3];
    const float* bt   = (const float*)d_in[4];
    const float* Kw   = (const float*)d_in[5];
    const float* Kb   = (const float*)d_in[6];
    const float* Qw   = (const float*)d_in[7];
    const float* Qb   = (const float*)d_in[8];
    const float* Vw   = (const float*)d_in[9];
    const float* Vb   = (const float*)d_in[10];
    const float* ln_g = (const float*)d_in[11];
    const float* ln_b = (const float*)d_in[12];
    float* out = (float*)d_out;

    cudaFuncSetAttribute(gemm_attn, cudaFuncAttributeMaxDynamicSharedMemorySize,
                         GEMM_SMEM_FLOATS * (int)sizeof(float));

    zero_scratch<<<2048, 256>>>();
    fold_w<<<256, 384>>>(Wt, Kw, Qw, Vw);
    fold_b<<<2, 384>>>(bt, Kw, Kb, Qw, Qb, Vw, Vb);

    for (int e = 0; e < 2; e++) {
        gemm_attn<<<NN / BM, 256, GEMM_SMEM_FLOATS * sizeof(float)>>>(feat, e);
        scatter_edges<<<(EE * 32) / 256, 256>>>(src + (size_t)e * EE, dst + (size_t)e * EE, e);
    }
    finalize<<<(NN * 32) / 256, 256>>>(feat, ln_g, ln_b, out);
}

// round 11
// speedup vs baseline: 2.0942x; 2.0942x over previous
#include <cuda_runtime.h>
#include <math.h>
#include <stdint.h>

#define NN   100000      // nodes
#define DD   128         // feature dim
#define EE   800000      // edges per etype
#define QKV  384         // q|k|v outputs per node per etype
#define BLKM 64          // nodes per CTA
#define T64  1563        // ceil(100000/64)

// ---------------- scratch ----------------
__device__ float g_Wf[2 * QKV * DD];            // folded weights TRANSPOSED: [e][j][k], tf32-rounded
__device__ float g_bias[2 * QKV];               // folded biases (fp32)
__device__ float g_Wh[2 * (size_t)NN * DD];     // per-etype attention output
__device__ float g_tot[2 * (size_t)NN * DD];    // per-etype scatter sums
__device__ float g_deg[2 * NN];                 // per-etype in-degrees

// ---------------- helpers ----------------
__device__ __forceinline__ float tf32r(float x) {
    uint32_t u;
    asm("cvt.rna.tf32.f32 %0, %1;" : "=r"(u) : "f"(x));
    return __uint_as_float(u);
}
__device__ __forceinline__ void mma_tf32(float* c, const uint32_t* a, const uint32_t* b) {
    asm volatile(
        "mma.sync.aligned.m16n8k8.row.col.f32.tf32.tf32.f32 "
        "{%0,%1,%2,%3}, {%4,%5,%6,%7}, {%8,%9}, {%0,%1,%2,%3};"
        : "+f"(c[0]), "+f"(c[1]), "+f"(c[2]), "+f"(c[3])
        : "r"(a[0]), "r"(a[1]), "r"(a[2]), "r"(a[3]), "r"(b[0]), "r"(b[1]));
}

// ---------------- zero scratch ----------------
__global__ void zero_scratch() {
    const size_t stride = (size_t)gridDim.x * blockDim.x;
    size_t i0 = (size_t)blockIdx.x * blockDim.x + threadIdx.x;
    float4 z = make_float4(0.f, 0.f, 0.f, 0.f);
    float4* t4 = reinterpret_cast<float4*>(g_tot);
    const size_t nt4 = (2 * (size_t)NN * DD) / 4;
    for (size_t i = i0; i < nt4; i += stride) t4[i] = z;
    float4* d4 = reinterpret_cast<float4*>(g_deg);
    const size_t nd4 = (2 * (size_t)NN) / 4;
    for (size_t i = i0; i < nd4; i += stride) d4[i] = z;
}

// ---------------- fold weights: Wf[e][j][k] = (Wt[e] @ Xw[e])^T, tf32-rounded ----------------
__global__ void fold_w(const float* __restrict__ Wt, const float* __restrict__ Kw,
                       const float* __restrict__ Qw, const float* __restrict__ Vw) {
    const int b = blockIdx.x;
    const int e = b >> 7, kk = b & 127;
    const int j = threadIdx.x;
    const int sel = j >> 7, jj = j & 127;
    const float* X = (sel == 0 ? Qw : (sel == 1 ? Kw : Vw)) + e * DD * DD;
    const float* wrow = Wt + e * DD * DD + kk * DD;
    float s = 0.f;
#pragma unroll 8
    for (int m = 0; m < DD; m++) s += wrow[m] * X[m * DD + jj];
    g_Wf[((size_t)e * QKV + j) * DD + kk] = tf32r(s);
}

// ---------------- fold biases ----------------
__global__ void fold_b(const float* __restrict__ bt,
                       const float* __restrict__ Kw, const float* __restrict__ Kb,
                       const float* __restrict__ Qw, const float* __restrict__ Qb,
                       const float* __restrict__ Vw, const float* __restrict__ Vb) {
    const int e = blockIdx.x;
    const int j = threadIdx.x;
    const int sel = j >> 7, jj = j & 127;
    const float* X  = (sel == 0 ? Qw : (sel == 1 ? Kw : Vw)) + e * DD * DD;
    const float* Xb = (sel == 0 ? Qb : (sel == 1 ? Kb : Vb)) + e * DD;
    float s = Xb[jj];
#pragma unroll 8
    for (int m = 0; m < DD; m++) s += bt[e * DD + m] * X[m * DD + jj];
    g_bias[e * QKV + j] = s;
}

// ---------------- mma.sync tf32 GEMM + fused cross-head attention ----------------
// CTA: 256 threads = 8 warps (2 M x 4 N). Tile: M=64 nodes, N=384, K=128.
// SMEM (bytes):
//   GEMM phase: As[64][132] @ 0 (33792) | Bs[384][36] @ 33792 (55296) -> 89088
//   EPI  phase: S[64][388]  @ 0 (99328)
//   sbias[384] @ 99328 (1536)  -> total 100864
#define AS_STRIDE 132
#define BS_STRIDE 36
#define S_STRIDE  388
#define BS_OFF    33792
#define SB_OFF    99328
#define SM_BYTES  100864

__global__ __launch_bounds__(256, 2) void gemm_attn(const float* __restrict__ feat) {
    extern __shared__ float sm[];
    float* As    = sm;                                // [64][132]
    float* Bs    = sm + BS_OFF / 4;                   // [384][36]
    float* S     = sm;                                // [64][388] (epilogue)
    float* sbias = sm + SB_OFF / 4;                   // [384]

    const int t    = threadIdx.x;
    const int lane = t & 31;
    const int g    = lane >> 2;       // 0..7
    const int tig  = lane & 3;        // 0..3
    const int wid  = t >> 5;
    const int wm   = wid >> 2;        // 0..1
    const int wn   = wid & 3;         // 0..3
    const int bid  = blockIdx.x;
    const int e    = bid >= T64;
    const int base = (bid - e * T64) * BLKM;

    // stage biases (region disjoint from GEMM buffers)
    for (int j = t; j < QKV; j += 256) sbias[j] = g_bias[e * QKV + j];

    // stage A = feat tile, tf32-rounded, row stride 132
    {
        const float4* fsrc = reinterpret_cast<const float4*>(feat);
        for (int idx = t; idx < BLKM * 32; idx += 256) {
            int r = idx >> 5, c4 = idx & 31;
            int node = base + r;
            float4 v = make_float4(0.f, 0.f, 0.f, 0.f);
            if (node < NN) v = fsrc[(size_t)node * 32 + c4];
            v.x = tf32r(v.x); v.y = tf32r(v.y); v.z = tf32r(v.z); v.w = tf32r(v.w);
            *reinterpret_cast<float4*>(As + r * AS_STRIDE + c4 * 4) = v;
        }
    }

    float acc[2][12][4];
#pragma unroll
    for (int mf = 0; mf < 2; mf++)
#pragma unroll
        for (int nf = 0; nf < 12; nf++)
#pragma unroll
            for (int i = 0; i < 4; i++) acc[mf][nf][i] = 0.f;

    const float4* Wf4 = reinterpret_cast<const float4*>(g_Wf + (size_t)e * QKV * DD);

    // K loop: 4 chunks of 32
    for (int kc = 0; kc < 4; kc++) {
        // load B chunk: Bs[j][kk] = Wf[j][kc*32+kk], row stride 36
        for (int idx = t; idx < QKV * 8; idx += 256) {
            int j = idx >> 3, c4 = idx & 7;
            float4 v = Wf4[(size_t)j * 32 + kc * 8 + c4];
            *reinterpret_cast<float4*>(Bs + j * BS_STRIDE + c4 * 4) = v;
        }
        __syncthreads();
#pragma unroll
        for (int k8 = 0; k8 < 4; k8++) {
            const int ko = kc * 32 + k8 * 8;
            uint32_t a[2][4];
#pragma unroll
            for (int mf = 0; mf < 2; mf++) {
                const float* ap = As + (wm * 32 + mf * 16 + g) * AS_STRIDE + ko + tig;
                a[mf][0] = __float_as_uint(ap[0]);
                a[mf][1] = __float_as_uint(ap[8 * AS_STRIDE]);
                a[mf][2] = __float_as_uint(ap[4]);
                a[mf][3] = __float_as_uint(ap[8 * AS_STRIDE + 4]);
            }
#pragma unroll
            for (int nf = 0; nf < 12; nf++) {
                const float* bp = Bs + (wn * 96 + nf * 8 + g) * BS_STRIDE + k8 * 8 + tig;
                uint32_t b[2];
                b[0] = __float_as_uint(bp[0]);
                b[1] = __float_as_uint(bp[4]);
                mma_tf32(acc[0][nf], a[0], b);
                mma_tf32(acc[1][nf], a[1], b);
            }
        }
        __syncthreads();
    }

    // ---- epilogue: store biased q|k|v to S[64][388] ----
#pragma unroll
    for (int mf = 0; mf < 2; mf++) {
        int row = wm * 32 + mf * 16 + g;
#pragma unroll
        for (int nf = 0; nf < 12; nf++) {
            int col = wn * 96 + nf * 8 + tig * 2;
            float b0 = sbias[col], b1 = sbias[col + 1];
            *reinterpret_cast<float2*>(S + row * S_STRIDE + col) =
                make_float2(acc[mf][nf][0] + b0, acc[mf][nf][1] + b1);
            *reinterpret_cast<float2*>(S + (row + 8) * S_STRIDE + col) =
                make_float2(acc[mf][nf][2] + b0, acc[mf][nf][3] + b1);
        }
    }
    __syncthreads();

    // ---- attention: 4 threads per node, thread = one head; H=4, HD=32 ----
    {
        const int node = t >> 2;
        const int h    = t & 3;
        const float* P = S + node * S_STRIDE;

        float qv[32];
#pragma unroll
        for (int d = 0; d < 32; d++) qv[d] = P[h * 32 + d];

        float sc[4];
#pragma unroll
        for (int gg = 0; gg < 4; gg++) {
            float s = 0.f;
#pragma unroll
            for (int d = 0; d < 32; d++) s += qv[d] * P[128 + gg * 32 + d];
            sc[gg] = s * 0.17677669529663687f;   // 1/sqrt(32)
        }
        float mx = fmaxf(fmaxf(sc[0], sc[1]), fmaxf(sc[2], sc[3]));
        float e0 = __expf(sc[0] - mx), e1 = __expf(sc[1] - mx);
        float e2 = __expf(sc[2] - mx), e3 = __expf(sc[3] - mx);
        float inv = 1.f / (e0 + e1 + e2 + e3);
        e0 *= inv; e1 *= inv; e2 *= inv; e3 *= inv;

        const int gn = base + node;
        if (gn < NN) {
            float o[32];
#pragma unroll
            for (int d = 0; d < 32; d++)
                o[d] = e0 * P[256 +  0 + d] + e1 * P[256 + 32 + d]
                     + e2 * P[256 + 64 + d] + e3 * P[256 + 96 + d];
            float* outp = g_Wh + ((size_t)e * NN + gn) * DD + h * 32;
#pragma unroll
            for (int q4 = 0; q4 < 8; q4++)
                *reinterpret_cast<float4*>(outp + q4 * 4) =
                    make_float4(o[q4*4], o[q4*4+1], o[q4*4+2], o[q4*4+3]);
        }
    }
}

// ---------------- edge scatter (both etypes): one warp per edge ----------------
__device__ __forceinline__ void red_add_v4(float* p, float4 v) {
    asm volatile("red.global.add.v4.f32 [%0], {%1,%2,%3,%4};"
                 :: "l"(p), "f"(v.x), "f"(v.y), "f"(v.z), "f"(v.w) : "memory");
}

__global__ void scatter_edges(const int* __restrict__ src, const int* __restrict__ dst) {
    const long long gw = ((long long)blockIdx.x * blockDim.x + threadIdx.x) >> 5;
    const int lane = threadIdx.x & 31;
    if (gw >= 2LL * EE) return;
    const int e   = gw >= EE;
    const size_t i = (size_t)gw;
    const int s = src[i];
    const int d = dst[i];
    if (lane == 0) atomicAdd(&g_deg[e * NN + d], 1.0f);
    const float4 v = *reinterpret_cast<const float4*>(g_Wh + ((size_t)e * NN + s) * DD + lane * 4);
    red_add_v4(g_tot + ((size_t)e * NN + d) * DD + lane * 4, v);
}

// ---------------- residual + mean + LayerNorm ----------------
__global__ void finalize(const float* __restrict__ feat,
                         const float* __restrict__ ln_g, const float* __restrict__ ln_b,
                         float* __restrict__ out) {
    const int node = (int)((blockIdx.x * (unsigned)blockDim.x + threadIdx.x) >> 5);
    const int lane = threadIdx.x & 31;
    if (node >= NN) return;
    const size_t off = (size_t)node * DD + lane * 4;
    float4 f  = *reinterpret_cast<const float4*>(feat + off);
    float4 t0 = *reinterpret_cast<const float4*>(g_tot + off);
    float4 t1 = *reinterpret_cast<const float4*>(g_tot + (size_t)NN * DD + off);
    float r0 = 1.f / fmaxf(g_deg[node], 1.f);
    float r1 = 1.f / fmaxf(g_deg[NN + node], 1.f);
    float h0 = f.x + t0.x * r0 + t1.x * r1;
    float h1 = f.y + t0.y * r0 + t1.y * r1;
    float h2 = f.z + t0.z * r0 + t1.z * r1;
    float h3 = f.w + t0.w * r0 + t1.w * r1;
    float sum = h0 + h1 + h2 + h3;
    float ssq = h0 * h0 + h1 * h1 + h2 * h2 + h3 * h3;
#pragma unroll
    for (int o = 16; o; o >>= 1) {
        sum += __shfl_xor_sync(0xffffffffu, sum, o);
        ssq += __shfl_xor_sync(0xffffffffu, ssq, o);
    }
    const float mu  = sum * (1.f / 128.f);
    const float var = ssq * (1.f / 128.f) - mu * mu;
    const float rs  = rsqrtf(var + 1e-5f);
    float4 g = *reinterpret_cast<const float4*>(ln_g + lane * 4);
    float4 b = *reinterpret_cast<const float4*>(ln_b + lane * 4);
    float4 o4;
    o4.x = (h0 - mu) * rs * g.x + b.x;
    o4.y = (h1 - mu) * rs * g.y + b.y;
    o4.z = (h2 - mu) * rs * g.z + b.z;
    o4.w = (h3 - mu) * rs * g.w + b.w;
    *reinterpret_cast<float4*>(out + off) = o4;
}

// ---------------- launch ----------------
extern "C" void kernel_launch(void* const* d_in, const int* in_sizes, int n_in,
                              void* d_out, int out_size) {
    const float* feat = (const float*)d_in[0];
    const int*   src  = (const int*)  d_in[1];
    const int*   dst  = (const int*)  d_in[2];
    const float* Wt   = (const float*)d_in[3];
    const float* bt   = (const float*)d_in[4];
    const float* Kw   = (const float*)d_in[5];
    const float* Kb   = (const float*)d_in[6];
    const float* Qw   = (const float*)d_in[7];
    const float* Qb   = (const float*)d_in[8];
    const float* Vw   = (const float*)d_in[9];
    const float* Vb   = (const float*)d_in[10];
    const float* ln_g = (const float*)d_in[11];
    const float* ln_b = (const float*)d_in[12];
    float* out = (float*)d_out;

    cudaFuncSetAttribute(gemm_attn, cudaFuncAttributeMaxDynamicSharedMemorySize, SM_BYTES);

    zero_scratch<<<2048, 256>>>();
    fold_w<<<256, 384>>>(Wt, Kw, Qw, Vw);
    fold_b<<<2, 384>>>(bt, Kw, Kb, Qw, Qb, Vw, Vb);

    gemm_attn<<<2 * T64, 256, SM_BYTES>>>(feat);

    scatter_edges<<<(2 * EE * 32) / 256, 256>>>(src, dst);
    finalize<<<(NN * 32 + 255) / 256, 256>>>(feat, ln_g, ln_b, out);
}